// round 7
// baseline (speedup 1.0000x reference)
#include <cuda_runtime.h>
#include <cuda_fp16.h>
#include <math.h>
#include <stdint.h>

// Problem constants
#define BB   8
#define TT   2048
#define EE   256
#define HH   4
#define HD   64
#define PP   8
#define BT   (BB*TT)          // 16384
#define NBH  (BB*HH)          // 32

// ---------------- scratch (device globals; no allocation allowed) -----------
__device__ float g_h[BT*EE];
__device__ float g_bs[BT];
__device__ float g_weff[EE+1];       // w_eff[256] + b_eff
__device__ float g_zp[HH][BT];       // per-head boundary partials
__device__ float g_chs[BB][32][EE];  // 64-token chunk sums of h
// fp16 hi/lo splits
__device__ __half g_xh[BT*EE], g_xl[BT*EE];
__device__ __half g_hh[BT*EE], g_hl[BT*EE];
__device__ __half g_wsh[4][EE*EE], g_wsl[4][EE*EE];   // w_in, w_q, w_k, w_v
// [bh][t][64] layouts
__device__ __half g_qh[NBH*TT*HD], g_ql[NBH*TT*HD];
__device__ __half g_kh[NBH*TT*HD], g_kl[NBH*TT*HD];
__device__ __half g_vh[NBH*TT*HD], g_vl[NBH*TT*HD];

// ============================ warp-mma helpers ==============================
__device__ __forceinline__ uint32_t smem_u32(const void* p) {
    uint32_t a;
    asm("{ .reg .u64 tmp; cvta.to.shared.u64 tmp, %1; cvt.u32.u64 %0, tmp; }"
        : "=r"(a) : "l"(p));
    return a;
}
__device__ __forceinline__ void ldmatrix_x4(uint32_t* r, uint32_t addr) {
    asm volatile("ldmatrix.sync.aligned.m8n8.x4.shared.b16 {%0,%1,%2,%3}, [%4];"
                 : "=r"(r[0]), "=r"(r[1]), "=r"(r[2]), "=r"(r[3]) : "r"(addr));
}
__device__ __forceinline__ void ldmatrix_x2(uint32_t* r, uint32_t addr) {
    asm volatile("ldmatrix.sync.aligned.m8n8.x2.shared.b16 {%0,%1}, [%2];"
                 : "=r"(r[0]), "=r"(r[1]) : "r"(addr));
}
__device__ __forceinline__ void ldmatrix_x2_trans(uint32_t* r, uint32_t addr) {
    asm volatile("ldmatrix.sync.aligned.m8n8.x2.trans.shared.b16 {%0,%1}, [%2];"
                 : "=r"(r[0]), "=r"(r[1]) : "r"(addr));
}
__device__ __forceinline__ void mma16816(float* d, const uint32_t* a, const uint32_t* b) {
    asm volatile(
        "mma.sync.aligned.m16n8k16.row.col.f32.f16.f16.f32 "
        "{%0,%1,%2,%3}, {%4,%5,%6,%7}, {%8,%9}, {%0,%1,%2,%3};"
        : "+f"(d[0]), "+f"(d[1]), "+f"(d[2]), "+f"(d[3])
        : "r"(a[0]), "r"(a[1]), "r"(a[2]), "r"(a[3]), "r"(b[0]), "r"(b[1]));
}
__device__ __forceinline__ uint32_t pack_half2(__half lo, __half hi) {
    return (uint32_t)__half_as_ushort(lo) | ((uint32_t)__half_as_ushort(hi) << 16);
}
#define CP_ASYNC16(smem, gptr) \
    asm volatile("cp.async.cg.shared.global [%0], [%1], 16;" :: "r"(smem), "l"(gptr))
#define CP_COMMIT() asm volatile("cp.async.commit_group;" ::: "memory")
#define CP_WAIT1()  asm volatile("cp.async.wait_group 1;" ::: "memory")
#define CP_WAIT0()  asm volatile("cp.async.wait_group 0;" ::: "memory")

// ---------------------------------------------------------------------------
// w_eff[j] = sum_i w_bd[i] * w_o[i][j];  b_eff = sum_i w_bd[i]*b_o[i] + b_bd
__global__ void weff_kernel(const float* __restrict__ w_o,
                            const float* __restrict__ w_bd,
                            const float* __restrict__ b_o,
                            const float* __restrict__ b_bd)
{
    int j = threadIdx.x;
    float s = 0.f;
    for (int i = 0; i < EE; i++) s += w_bd[i] * w_o[i*EE + j];
    g_weff[j] = s;
    if (j == 0) {
        float bb = b_bd[0];
        for (int i = 0; i < EE; i++) bb += w_bd[i] * b_o[i];
        g_weff[EE] = bb;
    }
}

// ---------------------------------------------------------------------------
// Generic fp32 -> fp16 hi/lo split (float4 granularity).
__global__ __launch_bounds__(256) void split_kernel(const float* __restrict__ src,
                                                    __half* __restrict__ dh,
                                                    __half* __restrict__ dl,
                                                    int n4)
{
    int i = blockIdx.x * 256 + threadIdx.x;
    if (i >= n4) return;
    float4 v = ((const float4*)src)[i];
    __half h0 = __float2half_rn(v.x), h1 = __float2half_rn(v.y);
    __half h2 = __float2half_rn(v.z), h3 = __float2half_rn(v.w);
    __half l0 = __float2half_rn(v.x - __half2float(h0));
    __half l1 = __float2half_rn(v.y - __half2float(h1));
    __half l2 = __float2half_rn(v.z - __half2float(h2));
    __half l3 = __float2half_rn(v.w - __half2float(h3));
    ((uint2*)dh)[i] = make_uint2(pack_half2(h0, h1), pack_half2(h2, h3));
    ((uint2*)dl)[i] = make_uint2(pack_half2(l0, l1), pack_half2(l2, l3));
}

// ---------------------------------------------------------------------------
// Tensor-core GEMM: C[m][n] = sum_k A[m][k]*W[n][k] + bias[n], fp16 3-MMA split.
__global__ __launch_bounds__(128) void gemm_tc(const __half* __restrict__ Ah,
                                               const __half* __restrict__ Al,
                                               const __half* __restrict__ Wh,
                                               const __half* __restrict__ Wl,
                                               const float* __restrict__ bias,
                                               float* __restrict__ outf,
                                               __half* __restrict__ oh,
                                               __half* __restrict__ ol,
                                               int mode)
{
    __shared__ __half Ash[64][72], Asl[64][72], Wsh[64][72], Wsl[64][72];
    const int m0 = blockIdx.x * 64;
    const int n0 = blockIdx.y * 64;
    const int tid = threadIdx.x;
    const int wid = tid >> 5;
    const int lane = tid & 31;
    const int g = lane >> 2, t4 = lane & 3;

    float acc[8][4];
#pragma unroll
    for (int i = 0; i < 8; i++)
#pragma unroll
        for (int j = 0; j < 4; j++) acc[i][j] = 0.f;

    const int arow = 16 * wid + (lane & 15);
    const int asel = (lane & 16) ? 8 : 0;
    const int brow = lane & 7;
    const int bsel = (lane & 8) ? 8 : 0;

    for (int kc0 = 0; kc0 < EE; kc0 += 64) {
        if (kc0) __syncthreads();
#pragma unroll
        for (int j = 0; j < 4; j++) {
            int i = tid + j * 128;            // 0..511
            int r = i >> 3, c = (i & 7) * 8;
            *(uint4*)&Ash[r][c] = *(const uint4*)&Ah[(size_t)(m0 + r) * EE + kc0 + c];
            *(uint4*)&Asl[r][c] = *(const uint4*)&Al[(size_t)(m0 + r) * EE + kc0 + c];
            *(uint4*)&Wsh[r][c] = *(const uint4*)&Wh[(size_t)(n0 + r) * EE + kc0 + c];
            *(uint4*)&Wsl[r][c] = *(const uint4*)&Wl[(size_t)(n0 + r) * EE + kc0 + c];
        }
        __syncthreads();

        uint32_t afh[4][4], afl[4][4];
#pragma unroll
        for (int kc = 0; kc < 4; kc++) {
            ldmatrix_x4(afh[kc], smem_u32(&Ash[arow][kc * 16 + asel]));
            ldmatrix_x4(afl[kc], smem_u32(&Asl[arow][kc * 16 + asel]));
        }
#pragma unroll
        for (int kc = 0; kc < 4; kc++) {
#pragma unroll
            for (int nb = 0; nb < 8; nb++) {
                uint32_t bh2[2], bl2[2];
                ldmatrix_x2(bh2, smem_u32(&Wsh[8 * nb + brow][kc * 16 + bsel]));
                ldmatrix_x2(bl2, smem_u32(&Wsl[8 * nb + brow][kc * 16 + bsel]));
                mma16816(acc[nb], afh[kc], bh2);
                mma16816(acc[nb], afh[kc], bl2);
                mma16816(acc[nb], afl[kc], bh2);
            }
        }
    }

    // epilogue
    const int r0 = m0 + 16 * wid + g;
    const int r1 = r0 + 8;
    const float scale = (mode == 1) ? 0.125f : 1.0f;
#pragma unroll
    for (int nb = 0; nb < 8; nb++) {
        int c0 = n0 + 8 * nb + 2 * t4;
        float bx = bias[c0], by = bias[c0 + 1];
        float v00 = acc[nb][0] + bx, v01 = acc[nb][1] + by;
        float v10 = acc[nb][2] + bx, v11 = acc[nb][3] + by;
        if (mode == 0) {
            *(float2*)&outf[(size_t)r0 * EE + c0] = make_float2(v00, v01);
            *(float2*)&outf[(size_t)r1 * EE + c0] = make_float2(v10, v11);
            __half h00 = __float2half_rn(v00), h01 = __float2half_rn(v01);
            __half h10 = __float2half_rn(v10), h11 = __float2half_rn(v11);
            *(uint32_t*)&oh[(size_t)r0 * EE + c0] = pack_half2(h00, h01);
            *(uint32_t*)&oh[(size_t)r1 * EE + c0] = pack_half2(h10, h11);
            *(uint32_t*)&ol[(size_t)r0 * EE + c0] =
                pack_half2(__float2half_rn(v00 - __half2float(h00)),
                           __float2half_rn(v01 - __half2float(h01)));
            *(uint32_t*)&ol[(size_t)r1 * EE + c0] =
                pack_half2(__float2half_rn(v10 - __half2float(h10)),
                           __float2half_rn(v11 - __half2float(h11)));
        } else {
            v00 *= scale; v01 *= scale; v10 *= scale; v11 *= scale;
            int hh = c0 >> 6, d = c0 & 63;
            int b = r0 >> 11, t0n = r0 & (TT - 1);
            size_t base = ((size_t)((b * HH + hh) * TT)) * HD + d;
            size_t i0 = base + (size_t)t0n * HD;
            size_t i1 = base + (size_t)(t0n + 8) * HD;
            __half h00 = __float2half_rn(v00), h01 = __float2half_rn(v01);
            __half h10 = __float2half_rn(v10), h11 = __float2half_rn(v11);
            *(uint32_t*)&oh[i0] = pack_half2(h00, h01);
            *(uint32_t*)&oh[i1] = pack_half2(h10, h11);
            *(uint32_t*)&ol[i0] =
                pack_half2(__float2half_rn(v00 - __half2float(h00)),
                           __float2half_rn(v01 - __half2float(h01)));
            *(uint32_t*)&ol[i1] =
                pack_half2(__float2half_rn(v10 - __half2float(h10)),
                           __float2half_rn(v11 - __half2float(h11)));
        }
    }
}

// ---------------------------------------------------------------------------
// 64-token chunk sums of h: g_chs[b][c][d] = sum_{t in chunk} h[b][t][d]
__global__ __launch_bounds__(256) void chs_kernel()
{
    int b = blockIdx.x, c = blockIdx.y, d = threadIdx.x;
    const float* p = g_h + ((size_t)b * TT + c * 64) * EE + d;
    float s = 0.f;
#pragma unroll 8
    for (int i = 0; i < 64; i++) s += p[(size_t)i * EE];
    g_chs[b][c][d] = s;
}

// ---------------------------------------------------------------------------
// Flash attention v2: 128 q rows / CTA, 8 warps, cp.async double-buffered K/V.
// fp16 3-MMA hi/lo split (fp32-accurate). No online rescaling (scores bounded).
// Epilogue: per-head boundary partial z = (O . w_eff_slice) / l -> g_zp.
struct AttnStage {
    __half kh[64][72];
    __half kl[64][72];
    __half vh[64][72];
    __half vl[64][72];
};
#define ATTN_SMEM (2 * (int)sizeof(AttnStage))   // 73728 bytes

__global__ __launch_bounds__(256) void attn_mma()
{
    extern __shared__ AttnStage stg[];   // stg[0..1]
    const int tid = threadIdx.x;
    const int wid = tid >> 5;
    const int lane = tid & 31;
    const int bh = blockIdx.y;
    const int qt0 = blockIdx.x * 128;
    const int b = bh >> 2, hh = bh & 3;
    const int g = lane >> 2, t4 = lane & 3;

    // ---- stage Q (128 rows, hi/lo) through stg[0], extract A-fragments ----
    {
        const uint4* Qh = (const uint4*)(g_qh + ((size_t)bh * TT + qt0) * HD);
        const uint4* Ql = (const uint4*)(g_ql + ((size_t)bh * TT + qt0) * HD);
#pragma unroll
        for (int i = tid; i < 1024; i += 256) {     // 128 rows x 8 chunks
            int r = i >> 3, c8 = i & 7;
            __half* dh = (r < 64) ? &stg[0].kh[r][c8 * 8] : &stg[0].kl[r - 64][c8 * 8];
            __half* dl = (r < 64) ? &stg[0].vh[r][c8 * 8] : &stg[0].vl[r - 64][c8 * 8];
            *(uint4*)dh = Qh[i];
            *(uint4*)dl = Ql[i];
        }
    }
    __syncthreads();

    uint32_t qfh[4][4], qfl[4][4];
    {
        const __half (*qsh)[72] = (wid < 4) ? stg[0].kh : stg[0].kl;
        const __half (*qsl)[72] = (wid < 4) ? stg[0].vh : stg[0].vl;
        int arow = 16 * (wid & 3) + (lane & 15);
        int acolsel = (lane & 16) ? 8 : 0;
#pragma unroll
        for (int kc = 0; kc < 4; kc++) {
            ldmatrix_x4(qfh[kc], smem_u32(&qsh[arow][kc * 16 + acolsel]));
            ldmatrix_x4(qfl[kc], smem_u32(&qsl[arow][kc * 16 + acolsel]));
        }
    }
    __syncthreads();

    float O[8][4];
#pragma unroll
    for (int i = 0; i < 8; i++)
#pragma unroll
        for (int j = 0; j < 4; j++) O[i][j] = 0.f;
    float lacc0 = 0.f, lacc8 = 0.f;

    const int brow = lane & 7;
    const int bcolsel = (lane & 8) ? 8 : 0;
    const int vrow = lane & 15;

    // prefetch tile 0 into stage 0
    {
        const size_t base = (size_t)bh * TT * HD;
        const __half* gs[4] = { g_kh + base, g_kl + base, g_vh + base, g_vl + base };
        __half* sd[4] = { &stg[0].kh[0][0], &stg[0].kl[0][0], &stg[0].vh[0][0], &stg[0].vl[0][0] };
#pragma unroll
        for (int i = tid; i < 2048; i += 256) {
            int a = i >> 9, j = i & 511, r = j >> 3, c8 = j & 7;
            CP_ASYNC16(smem_u32(sd[a] + r * 72 + c8 * 8), gs[a] + r * 64 + c8 * 8);
        }
        CP_COMMIT();
    }

    for (int kt = 0; kt < TT / 64; kt++) {
        const int cur = kt & 1;
        if (kt + 1 < TT / 64) {
            const size_t base = ((size_t)bh * TT + (kt + 1) * 64) * HD;
            const __half* gs[4] = { g_kh + base, g_kl + base, g_vh + base, g_vl + base };
            AttnStage* ns = &stg[cur ^ 1];
            __half* sd[4] = { &ns->kh[0][0], &ns->kl[0][0], &ns->vh[0][0], &ns->vl[0][0] };
#pragma unroll
            for (int i = tid; i < 2048; i += 256) {
                int a = i >> 9, j = i & 511, r = j >> 3, c8 = j & 7;
                CP_ASYNC16(smem_u32(sd[a] + r * 72 + c8 * 8), gs[a] + r * 64 + c8 * 8);
            }
            CP_COMMIT();
            CP_WAIT1();
        } else {
            CP_WAIT0();
        }
        __syncthreads();
        const AttnStage* st = &stg[cur];

        // ---- S = Q K^T, 3-way split ----
        float S[8][4];
#pragma unroll
        for (int i = 0; i < 8; i++)
#pragma unroll
            for (int j = 0; j < 4; j++) S[i][j] = 0.f;
#pragma unroll
        for (int kc = 0; kc < 4; kc++) {
#pragma unroll
            for (int nb = 0; nb < 8; nb++) {
                uint32_t bfh[2], bfl[2];
                ldmatrix_x2(bfh, smem_u32(&st->kh[8 * nb + brow][16 * kc + bcolsel]));
                ldmatrix_x2(bfl, smem_u32(&st->kl[8 * nb + brow][16 * kc + bcolsel]));
                mma16816(S[nb], qfh[kc], bfh);
                mma16816(S[nb], qfh[kc], bfl);
                mma16816(S[nb], qfl[kc], bfh);
            }
        }

        // ---- p = exp(s); accumulate l; build P fragments (hi/lo) ----
        uint32_t pfh[4][4], pfl[4][4];
#pragma unroll
        for (int nb = 0; nb < 8; nb++) {
            float p0 = __expf(S[nb][0]);
            float p1 = __expf(S[nb][1]);
            float p2 = __expf(S[nb][2]);
            float p3 = __expf(S[nb][3]);
            lacc0 += p0 + p1;
            lacc8 += p2 + p3;
            __half h0 = __float2half_rn(p0), h1 = __float2half_rn(p1);
            __half h2 = __float2half_rn(p2), h3 = __float2half_rn(p3);
            __half e0 = __float2half_rn(p0 - __half2float(h0));
            __half e1 = __float2half_rn(p1 - __half2float(h1));
            __half e2 = __float2half_rn(p2 - __half2float(h2));
            __half e3 = __float2half_rn(p3 - __half2float(h3));
            int c = nb >> 1, odd = nb & 1;
            pfh[c][2 * odd + 0] = pack_half2(h0, h1);
            pfh[c][2 * odd + 1] = pack_half2(h2, h3);
            pfl[c][2 * odd + 0] = pack_half2(e0, e1);
            pfl[c][2 * odd + 1] = pack_half2(e2, e3);
        }

        // ---- O += P V, 3-way split ----
#pragma unroll
        for (int db = 0; db < 8; db++) {
#pragma unroll
            for (int c = 0; c < 4; c++) {
                uint32_t bvh[2], bvl[2];
                ldmatrix_x2_trans(bvh, smem_u32(&st->vh[16 * c + vrow][8 * db]));
                ldmatrix_x2_trans(bvl, smem_u32(&st->vl[16 * c + vrow][8 * db]));
                mma16816(O[db], pfh[c], bvh);
                mma16816(O[db], pfh[c], bvl);
                mma16816(O[db], pfl[c], bvh);
            }
        }
        __syncthreads();
    }

    // reduce l across the 4 lanes of each row group
#pragma unroll
    for (int m = 1; m <= 2; m <<= 1) {
        lacc0 += __shfl_xor_sync(0xffffffffu, lacc0, m);
        lacc8 += __shfl_xor_sync(0xffffffffu, lacc8, m);
    }
    const float inv0 = 1.0f / lacc0;
    const float inv8 = 1.0f / lacc8;

    // ---- epilogue: z = (O . w_eff_slice) / l per row, reduce quad, store ----
    const float* wep = g_weff + hh * HD;
    float z0 = 0.f, z8 = 0.f;
#pragma unroll
    for (int db = 0; db < 8; db++) {
        float2 we2 = *(const float2*)(wep + 8 * db + 2 * t4);
        z0 += O[db][0] * we2.x + O[db][1] * we2.y;
        z8 += O[db][2] * we2.x + O[db][3] * we2.y;
    }
    z0 *= inv0; z8 *= inv8;
#pragma unroll
    for (int m = 1; m <= 2; m <<= 1) {
        z0 += __shfl_xor_sync(0xffffffffu, z0, m);
        z8 += __shfl_xor_sync(0xffffffffu, z8, m);
    }
    if (t4 == 0) {
        int row = qt0 + 16 * wid + g;
        g_zp[hh][b * TT + row] = z0;
        g_zp[hh][b * TT + row + 8] = z8;
    }
}

// ---------------------------------------------------------------------------
// bs[t] = sigmoid(sum_h zp[h][t] + b_eff)
__global__ __launch_bounds__(256) void zsig_kernel()
{
    int t = blockIdx.x * 256 + threadIdx.x;
    float z = g_zp[0][t] + g_zp[1][t] + g_zp[2][t] + g_zp[3][t] + g_weff[EE];
    g_bs[t] = 1.0f / (1.0f + expf(-z));
}

// ---------------------------------------------------------------------------
// Per batch: fp64 cumsum -> pid -> segment means (chunk sums + edges) -> proj
__global__ __launch_bounds__(256) void finalize_kernel(const float* __restrict__ w_pr,
                                                       const float* __restrict__ b_pr,
                                                       float* __restrict__ out)
{
    __shared__ float  sc[TT];
    __shared__ double sd[TT];
    __shared__ double part[256];
    __shared__ unsigned char pids[TT];
    __shared__ int starts[PP + 1];
    __shared__ float pe[PP][EE];

    const int b = blockIdx.x;
    const int tid = threadIdx.x;

    for (int t = tid; t < TT; t += 256) sc[t] = g_bs[b * TT + t];
    __syncthreads();

    {
        double s = 0.0;
#pragma unroll
        for (int i = 0; i < 8; i++) s += (double)sc[tid * 8 + i];
        part[tid] = s;
    }
    __syncthreads();
    if (tid == 0) {
        double run = 0.0;
        for (int i = 0; i < 256; i++) { double v = part[i]; part[i] = run; run += v; }
    }
    __syncthreads();
    {
        double c = part[tid];
#pragma unroll
        for (int i = 0; i < 8; i++) { c += (double)sc[tid * 8 + i]; sd[tid * 8 + i] = c; }
    }
    __syncthreads();

    double total = sd[TT - 1];
    double inv = 1.0 / fmax(total, 1e-6);
    for (int t = tid; t < TT; t += 256) {
        int p = (int)(sd[t] * inv * (double)PP);
        pids[t] = (unsigned char)(p > PP - 1 ? PP - 1 : p);
    }
    __syncthreads();

    if (tid == 0) {
        int cur = pids[0];
        for (int p = 0; p <= cur; p++) starts[p] = 0;
        for (int t = 1; t < TT; t++) {
            int p = pids[t];
            while (cur < p) starts[++cur] = t;
        }
        while (cur < PP) starts[++cur] = TT;
    }
    __syncthreads();

    // segment means via chunk sums + edge tokens; thread owns dim d = tid
    const float* hb = g_h + (size_t)b * TT * EE;
    for (int p = 0; p < PP; p++) {
        int s0 = starts[p], s1 = starts[p + 1];
        float sum = 0.f;
        int cs = (s0 + 63) >> 6, ce = s1 >> 6;
        if (cs <= ce) {
            for (int c = cs; c < ce; c++) sum += g_chs[b][c][tid];
            for (int t = s0; t < cs * 64; t++) sum += hb[(size_t)t * EE + tid];
            for (int t = ce * 64; t < s1; t++) sum += hb[(size_t)t * EE + tid];
        } else {
            for (int t = s0; t < s1; t++) sum += hb[(size_t)t * EE + tid];
        }
        float cnt = (float)(s1 - s0);
        pe[p][tid] = sum / fmaxf(cnt, 1.0f);
    }
    __syncthreads();

    // out[b][p][n] = pe[p].w_pr[n] + b_pr[n]; thread owns n = tid
    float bn = b_pr[tid];
    const float* wrow = w_pr + (size_t)tid * EE;
    for (int p = 0; p < PP; p++) {
        float a0 = 0.f, a1 = 0.f;
#pragma unroll 8
        for (int d = 0; d < EE; d += 2) {
            a0 += pe[p][d]     * wrow[d];
            a1 += pe[p][d + 1] * wrow[d + 1];
        }
        out[(size_t)(b * PP + p) * EE + tid] = bn + a0 + a1;
    }
}

// ---------------------------------------------------------------------------
extern "C" void kernel_launch(void* const* d_in, const int* in_sizes, int n_in,
                              void* d_out, int out_size)
{
    const float* x    = (const float*)d_in[0];
    const float* w_in = (const float*)d_in[1];
    const float* b_in = (const float*)d_in[2];
    const float* w_q  = (const float*)d_in[3];
    const float* b_q  = (const float*)d_in[4];
    const float* w_k  = (const float*)d_in[5];
    const float* b_k  = (const float*)d_in[6];
    const float* w_v  = (const float*)d_in[7];
    const float* b_v  = (const float*)d_in[8];
    const float* w_o  = (const float*)d_in[9];
    const float* b_o  = (const float*)d_in[10];
    const float* w_bd = (const float*)d_in[11];
    const float* b_bd = (const float*)d_in[12];
    const float* w_pr = (const float*)d_in[13];
    const float* b_pr = (const float*)d_in[14];
    float* out = (float*)d_out;

    float *ph;
    __half *pxh, *pxl, *phh, *phl, *pwh, *pwl;
    __half *pqh, *pql, *pkh, *pkl, *pvh, *pvl;
    cudaGetSymbolAddress((void**)&ph,  g_h);
    cudaGetSymbolAddress((void**)&pxh, g_xh);
    cudaGetSymbolAddress((void**)&pxl, g_xl);
    cudaGetSymbolAddress((void**)&phh, g_hh);
    cudaGetSymbolAddress((void**)&phl, g_hl);
    cudaGetSymbolAddress((void**)&pwh, g_wsh);
    cudaGetSymbolAddress((void**)&pwl, g_wsl);
    cudaGetSymbolAddress((void**)&pqh, g_qh);
    cudaGetSymbolAddress((void**)&pql, g_ql);
    cudaGetSymbolAddress((void**)&pkh, g_kh);
    cudaGetSymbolAddress((void**)&pkl, g_kl);
    cudaGetSymbolAddress((void**)&pvh, g_vh);
    cudaGetSymbolAddress((void**)&pvl, g_vl);

    static int smem_set = 0;
    if (!smem_set) {
        cudaFuncSetAttribute(attn_mma, cudaFuncAttributeMaxDynamicSharedMemorySize,
                             ATTN_SMEM);
        smem_set = 1;
    }

    weff_kernel<<<1, 256>>>(w_o, w_bd, b_o, b_bd);

    // splits
    split_kernel<<<BT*EE/4/256, 256>>>(x, pxh, pxl, BT*EE/4);
    split_kernel<<<EE*EE/4/256, 256>>>(w_in, pwh + 0*EE*EE, pwl + 0*EE*EE, EE*EE/4);
    split_kernel<<<EE*EE/4/256, 256>>>(w_q,  pwh + 1*EE*EE, pwl + 1*EE*EE, EE*EE/4);
    split_kernel<<<EE*EE/4/256, 256>>>(w_k,  pwh + 2*EE*EE, pwl + 2*EE*EE, EE*EE/4);
    split_kernel<<<EE*EE/4/256, 256>>>(w_v,  pwh + 3*EE*EE, pwl + 3*EE*EE, EE*EE/4);

    dim3 ggrid(BT / 64, EE / 64);
    // h = x @ w_in^T + b_in   (also emits hi/lo split of h)
    gemm_tc<<<ggrid, 128>>>(pxh, pxl, pwh + 0*EE*EE, pwl + 0*EE*EE, b_in, ph, phh, phl, 0);
    chs_kernel<<<dim3(BB, 32), 256>>>();
    // q, k, v
    gemm_tc<<<ggrid, 128>>>(phh, phl, pwh + 1*EE*EE, pwl + 1*EE*EE, b_q, nullptr, pqh, pql, 1);
    gemm_tc<<<ggrid, 128>>>(phh, phl, pwh + 2*EE*EE, pwl + 2*EE*EE, b_k, nullptr, pkh, pkl, 2);
    gemm_tc<<<ggrid, 128>>>(phh, phl, pwh + 3*EE*EE, pwl + 3*EE*EE, b_v, nullptr, pvh, pvl, 2);

    attn_mma<<<dim3(TT / 128, NBH), 256, ATTN_SMEM>>>();

    zsig_kernel<<<BT / 256, 256>>>();

    finalize_kernel<<<BB, 256>>>(w_pr, b_pr, out);
}

// round 8
// speedup vs baseline: 1.4000x; 1.4000x over previous
#include <cuda_runtime.h>
#include <cuda_fp16.h>
#include <math.h>
#include <stdint.h>

// Problem constants
#define BB   8
#define TT   2048
#define EE   256
#define HH   4
#define HD   64
#define PP   8
#define BT   (BB*TT)          // 16384
#define NBH  (BB*HH)          // 32

// ---------------- scratch (device globals; no allocation allowed) -----------
__device__ float g_h[BT*EE];
__device__ float g_bs[BT];
__device__ float g_weff[EE+1];       // w_eff[256] + b_eff
__device__ float g_zp[HH][BT];       // per-head boundary partials
__device__ float g_chs[BB][32][EE];  // 64-token chunk sums of h
__device__ float g_u[NBH*TT];        // u[bh][t] = v[bh][t] . w_eff_slice(h)
// fp16 hi/lo splits
__device__ __half g_xh[BT*EE], g_xl[BT*EE];
__device__ __half g_hh[BT*EE], g_hl[BT*EE];
__device__ __half g_wsh[4][EE*EE], g_wsl[4][EE*EE];   // w_in, w_q, w_k, w_v
// [bh][t][64] layouts
__device__ __half g_qh[NBH*TT*HD], g_ql[NBH*TT*HD];
__device__ __half g_kh[NBH*TT*HD], g_kl[NBH*TT*HD];

// ============================ warp-mma helpers ==============================
__device__ __forceinline__ uint32_t smem_u32(const void* p) {
    uint32_t a;
    asm("{ .reg .u64 tmp; cvta.to.shared.u64 tmp, %1; cvt.u32.u64 %0, tmp; }"
        : "=r"(a) : "l"(p));
    return a;
}
__device__ __forceinline__ void ldmatrix_x4(uint32_t* r, uint32_t addr) {
    asm volatile("ldmatrix.sync.aligned.m8n8.x4.shared.b16 {%0,%1,%2,%3}, [%4];"
                 : "=r"(r[0]), "=r"(r[1]), "=r"(r[2]), "=r"(r[3]) : "r"(addr));
}
__device__ __forceinline__ void ldmatrix_x2(uint32_t* r, uint32_t addr) {
    asm volatile("ldmatrix.sync.aligned.m8n8.x2.shared.b16 {%0,%1}, [%2];"
                 : "=r"(r[0]), "=r"(r[1]) : "r"(addr));
}
__device__ __forceinline__ void mma16816(float* d, const uint32_t* a, const uint32_t* b) {
    asm volatile(
        "mma.sync.aligned.m16n8k16.row.col.f32.f16.f16.f32 "
        "{%0,%1,%2,%3}, {%4,%5,%6,%7}, {%8,%9}, {%0,%1,%2,%3};"
        : "+f"(d[0]), "+f"(d[1]), "+f"(d[2]), "+f"(d[3])
        : "r"(a[0]), "r"(a[1]), "r"(a[2]), "r"(a[3]), "r"(b[0]), "r"(b[1]));
}
__device__ __forceinline__ uint32_t pack_half2(__half lo, __half hi) {
    return (uint32_t)__half_as_ushort(lo) | ((uint32_t)__half_as_ushort(hi) << 16);
}

// ---------------------------------------------------------------------------
// w_eff[j] = sum_i w_bd[i] * w_o[i][j];  b_eff = sum_i w_bd[i]*b_o[i] + b_bd
__global__ void weff_kernel(const float* __restrict__ w_o,
                            const float* __restrict__ w_bd,
                            const float* __restrict__ b_o,
                            const float* __restrict__ b_bd)
{
    int j = threadIdx.x;
    float s = 0.f;
    for (int i = 0; i < EE; i++) s += w_bd[i] * w_o[i*EE + j];
    g_weff[j] = s;
    if (j == 0) {
        float bb = b_bd[0];
        for (int i = 0; i < EE; i++) bb += w_bd[i] * b_o[i];
        g_weff[EE] = bb;
    }
}

// ---------------------------------------------------------------------------
// Generic fp32 -> fp16 hi/lo split (float4 granularity).
__global__ __launch_bounds__(256) void split_kernel(const float* __restrict__ src,
                                                    __half* __restrict__ dh,
                                                    __half* __restrict__ dl,
                                                    int n4)
{
    int i = blockIdx.x * 256 + threadIdx.x;
    if (i >= n4) return;
    float4 v = ((const float4*)src)[i];
    __half h0 = __float2half_rn(v.x), h1 = __float2half_rn(v.y);
    __half h2 = __float2half_rn(v.z), h3 = __float2half_rn(v.w);
    __half l0 = __float2half_rn(v.x - __half2float(h0));
    __half l1 = __float2half_rn(v.y - __half2float(h1));
    __half l2 = __float2half_rn(v.z - __half2float(h2));
    __half l3 = __float2half_rn(v.w - __half2float(h3));
    ((uint2*)dh)[i] = make_uint2(pack_half2(h0, h1), pack_half2(h2, h3));
    ((uint2*)dl)[i] = make_uint2(pack_half2(l0, l1), pack_half2(l2, l3));
}

// ---------------------------------------------------------------------------
// Tensor-core GEMM: C[m][n] = sum_k A[m][k]*W[n][k] + bias[n], fp16 3-MMA split.
// CTA: 128 threads (4 warps), tile 64(m) x 64(n). Grid: (M/64, 256/64).
// mode 0: fp32 to outf + hi/lo split to oh/ol (row-major [m][256]).
// mode 1: q -> oh/ol at [bh][t][d], scaled by 0.125.
// mode 2: k -> oh/ol at [bh][t][d].
// mode 3: v -> u[bh][t] = (v row) . g_weff slice   (no v materialization)
__global__ __launch_bounds__(128) void gemm_tc(const __half* __restrict__ Ah,
                                               const __half* __restrict__ Al,
                                               const __half* __restrict__ Wh,
                                               const __half* __restrict__ Wl,
                                               const float* __restrict__ bias,
                                               float* __restrict__ outf,
                                               __half* __restrict__ oh,
                                               __half* __restrict__ ol,
                                               int mode)
{
    __shared__ __half Ash[64][72], Asl[64][72], Wsh[64][72], Wsl[64][72];
    const int m0 = blockIdx.x * 64;
    const int n0 = blockIdx.y * 64;
    const int tid = threadIdx.x;
    const int wid = tid >> 5;
    const int lane = tid & 31;
    const int g = lane >> 2, t4 = lane & 3;

    float acc[8][4];
#pragma unroll
    for (int i = 0; i < 8; i++)
#pragma unroll
        for (int j = 0; j < 4; j++) acc[i][j] = 0.f;

    const int arow = 16 * wid + (lane & 15);
    const int asel = (lane & 16) ? 8 : 0;
    const int brow = lane & 7;
    const int bsel = (lane & 8) ? 8 : 0;

    for (int kc0 = 0; kc0 < EE; kc0 += 64) {
        if (kc0) __syncthreads();
#pragma unroll
        for (int j = 0; j < 4; j++) {
            int i = tid + j * 128;            // 0..511
            int r = i >> 3, c = (i & 7) * 8;
            *(uint4*)&Ash[r][c] = *(const uint4*)&Ah[(size_t)(m0 + r) * EE + kc0 + c];
            *(uint4*)&Asl[r][c] = *(const uint4*)&Al[(size_t)(m0 + r) * EE + kc0 + c];
            *(uint4*)&Wsh[r][c] = *(const uint4*)&Wh[(size_t)(n0 + r) * EE + kc0 + c];
            *(uint4*)&Wsl[r][c] = *(const uint4*)&Wl[(size_t)(n0 + r) * EE + kc0 + c];
        }
        __syncthreads();

        uint32_t afh[4][4], afl[4][4];
#pragma unroll
        for (int kc = 0; kc < 4; kc++) {
            ldmatrix_x4(afh[kc], smem_u32(&Ash[arow][kc * 16 + asel]));
            ldmatrix_x4(afl[kc], smem_u32(&Asl[arow][kc * 16 + asel]));
        }
#pragma unroll
        for (int kc = 0; kc < 4; kc++) {
#pragma unroll
            for (int nb = 0; nb < 8; nb++) {
                uint32_t bh2[2], bl2[2];
                ldmatrix_x2(bh2, smem_u32(&Wsh[8 * nb + brow][kc * 16 + bsel]));
                ldmatrix_x2(bl2, smem_u32(&Wsl[8 * nb + brow][kc * 16 + bsel]));
                mma16816(acc[nb], afh[kc], bh2);
                mma16816(acc[nb], afh[kc], bl2);
                mma16816(acc[nb], afl[kc], bh2);
            }
        }
    }

    // epilogue
    const int r0 = m0 + 16 * wid + g;
    const int r1 = r0 + 8;
    if (mode == 0) {
#pragma unroll
        for (int nb = 0; nb < 8; nb++) {
            int c0 = n0 + 8 * nb + 2 * t4;
            float bx = bias[c0], by = bias[c0 + 1];
            float v00 = acc[nb][0] + bx, v01 = acc[nb][1] + by;
            float v10 = acc[nb][2] + bx, v11 = acc[nb][3] + by;
            *(float2*)&outf[(size_t)r0 * EE + c0] = make_float2(v00, v01);
            *(float2*)&outf[(size_t)r1 * EE + c0] = make_float2(v10, v11);
            __half h00 = __float2half_rn(v00), h01 = __float2half_rn(v01);
            __half h10 = __float2half_rn(v10), h11 = __float2half_rn(v11);
            *(uint32_t*)&oh[(size_t)r0 * EE + c0] = pack_half2(h00, h01);
            *(uint32_t*)&oh[(size_t)r1 * EE + c0] = pack_half2(h10, h11);
            *(uint32_t*)&ol[(size_t)r0 * EE + c0] =
                pack_half2(__float2half_rn(v00 - __half2float(h00)),
                           __float2half_rn(v01 - __half2float(h01)));
            *(uint32_t*)&ol[(size_t)r1 * EE + c0] =
                pack_half2(__float2half_rn(v10 - __half2float(h10)),
                           __float2half_rn(v11 - __half2float(h11)));
        }
    } else if (mode == 3) {
        float z0 = 0.f, z1 = 0.f;
#pragma unroll
        for (int nb = 0; nb < 8; nb++) {
            int c0 = n0 + 8 * nb + 2 * t4;
            float bx = bias[c0], by = bias[c0 + 1];
            float wx = g_weff[c0], wy = g_weff[c0 + 1];
            z0 += (acc[nb][0] + bx) * wx + (acc[nb][1] + by) * wy;
            z1 += (acc[nb][2] + bx) * wx + (acc[nb][3] + by) * wy;
        }
#pragma unroll
        for (int m = 1; m <= 2; m <<= 1) {
            z0 += __shfl_xor_sync(0xffffffffu, z0, m);
            z1 += __shfl_xor_sync(0xffffffffu, z1, m);
        }
        if (t4 == 0) {
            int hh = n0 >> 6;
            int b = r0 >> 11, t = r0 & (TT - 1);
            size_t base = (size_t)(b * HH + hh) * TT;
            g_u[base + t] = z0;
            g_u[base + t + 8] = z1;
        }
    } else {
        const float scale = (mode == 1) ? 0.125f : 1.0f;
#pragma unroll
        for (int nb = 0; nb < 8; nb++) {
            int c0 = n0 + 8 * nb + 2 * t4;
            float bx = bias[c0], by = bias[c0 + 1];
            float v00 = (acc[nb][0] + bx) * scale, v01 = (acc[nb][1] + by) * scale;
            float v10 = (acc[nb][2] + bx) * scale, v11 = (acc[nb][3] + by) * scale;
            int hh = c0 >> 6, d = c0 & 63;
            int b = r0 >> 11, t0n = r0 & (TT - 1);
            size_t base = ((size_t)((b * HH + hh) * TT)) * HD + d;
            size_t i0 = base + (size_t)t0n * HD;
            size_t i1 = base + (size_t)(t0n + 8) * HD;
            __half h00 = __float2half_rn(v00), h01 = __float2half_rn(v01);
            __half h10 = __float2half_rn(v10), h11 = __float2half_rn(v11);
            *(uint32_t*)&oh[i0] = pack_half2(h00, h01);
            *(uint32_t*)&oh[i1] = pack_half2(h10, h11);
            *(uint32_t*)&ol[i0] =
                pack_half2(__float2half_rn(v00 - __half2float(h00)),
                           __float2half_rn(v01 - __half2float(h01)));
            *(uint32_t*)&ol[i1] =
                pack_half2(__float2half_rn(v10 - __half2float(h10)),
                           __float2half_rn(v11 - __half2float(h11)));
        }
    }
}

// ---------------------------------------------------------------------------
// 64-token chunk sums of h: g_chs[b][c][d] = sum_{t in chunk} h[b][t][d]
__global__ __launch_bounds__(256) void chs_kernel()
{
    int b = blockIdx.x, c = blockIdx.y, d = threadIdx.x;
    const float* p = g_h + ((size_t)b * TT + c * 64) * EE + d;
    float s = 0.f;
#pragma unroll 8
    for (int i = 0; i < 64; i++) s += p[(size_t)i * EE];
    g_chs[b][c][d] = s;
}

// ---------------------------------------------------------------------------
// Flash attention, S-only: z[t] = (sum_kv p*u) / (sum_kv p), p = exp(q.k/8).
// fp16 3-MMA hi/lo split for S (fp32-accurate). No PV GEMM, no V loads.
// CTA: 128 threads (4 warps), 64 query rows; warp w owns rows [16w,16w+16).
struct AttnSmem {
    __half kh[64][72];
    __half kl[64][72];
    float u[64];
};

__global__ __launch_bounds__(128) void attn_mma()
{
    __shared__ AttnSmem sm;
    const int tid = threadIdx.x;
    const int wid = tid >> 5;
    const int lane = tid & 31;
    const int bh = blockIdx.y;
    const int qt0 = blockIdx.x * 64;
    const int b = bh >> 2, hh = bh & 3;
    const int g = lane >> 2, t4 = lane & 3;

    // ---- stage Q (hi/lo) into kh/kl, extract A-fragments ----
    {
        const uint4* Qh = (const uint4*)(g_qh + ((size_t)bh * TT + qt0) * HD);
        const uint4* Ql = (const uint4*)(g_ql + ((size_t)bh * TT + qt0) * HD);
#pragma unroll
        for (int i = tid; i < 512; i += 128) {
            int r = i >> 3, c8 = i & 7;
            *(uint4*)&sm.kh[r][c8 * 8] = Qh[i];
            *(uint4*)&sm.kl[r][c8 * 8] = Ql[i];
        }
    }
    __syncthreads();

    uint32_t qfh[4][4], qfl[4][4];
    {
        int arow = 16 * wid + (lane & 15);
        int acolsel = (lane & 16) ? 8 : 0;
#pragma unroll
        for (int kc = 0; kc < 4; kc++) {
            ldmatrix_x4(qfh[kc], smem_u32(&sm.kh[arow][kc * 16 + acolsel]));
            ldmatrix_x4(qfl[kc], smem_u32(&sm.kl[arow][kc * 16 + acolsel]));
        }
    }
    __syncthreads();

    float lacc0 = 0.f, lacc8 = 0.f, zn0 = 0.f, zn8 = 0.f;

    // B-operand x4 addressing: lanes 0-15 -> nb block, lanes 16-31 -> nb+1 block
    const int brow4 = ((lane & 16) ? 8 : 0) + (lane & 7);
    const int bsel8 = (lane & 8) ? 8 : 0;

    for (int kt = 0; kt < TT / 64; kt++) {
        // ---- load K tile (hi/lo) + u segment ----
        {
            const size_t base = ((size_t)bh * TT + kt * 64) * HD;
            const uint4* Kh = (const uint4*)(g_kh + base);
            const uint4* Kl = (const uint4*)(g_kl + base);
#pragma unroll
            for (int i = tid; i < 512; i += 128) {
                int r = i >> 3, c8 = i & 7;
                *(uint4*)&sm.kh[r][c8 * 8] = Kh[i];
                *(uint4*)&sm.kl[r][c8 * 8] = Kl[i];
            }
            if (tid < 16)
                *(float4*)&sm.u[tid * 4] =
                    *(const float4*)&g_u[(size_t)bh * TT + kt * 64 + tid * 4];
        }
        __syncthreads();

        // ---- S = Q K^T, 3-way split, x4 B-loads over nb pairs ----
        float S[8][4];
#pragma unroll
        for (int i = 0; i < 8; i++)
#pragma unroll
            for (int j = 0; j < 4; j++) S[i][j] = 0.f;
#pragma unroll
        for (int kc = 0; kc < 4; kc++) {
#pragma unroll
            for (int nbp = 0; nbp < 4; nbp++) {
                uint32_t bf4[4], bl4[4];
                ldmatrix_x4(bf4, smem_u32(&sm.kh[16 * nbp + brow4][16 * kc + bsel8]));
                ldmatrix_x4(bl4, smem_u32(&sm.kl[16 * nbp + brow4][16 * kc + bsel8]));
                mma16816(S[2 * nbp],     qfh[kc], bf4);
                mma16816(S[2 * nbp],     qfh[kc], bl4);
                mma16816(S[2 * nbp],     qfl[kc], bf4);
                mma16816(S[2 * nbp + 1], qfh[kc], bf4 + 2);
                mma16816(S[2 * nbp + 1], qfh[kc], bl4 + 2);
                mma16816(S[2 * nbp + 1], qfl[kc], bf4 + 2);
            }
        }

        // ---- p = exp(s); accumulate l and z-numerator ----
#pragma unroll
        for (int nb = 0; nb < 8; nb++) {
            float2 uu = *(const float2*)&sm.u[8 * nb + 2 * t4];
            float p0 = __expf(S[nb][0]);
            float p1 = __expf(S[nb][1]);
            float p2 = __expf(S[nb][2]);
            float p3 = __expf(S[nb][3]);
            lacc0 += p0 + p1;
            lacc8 += p2 + p3;
            zn0 += p0 * uu.x + p1 * uu.y;
            zn8 += p2 * uu.x + p3 * uu.y;
        }
        __syncthreads();
    }

    // reduce across the 4 lanes of each row group
#pragma unroll
    for (int m = 1; m <= 2; m <<= 1) {
        lacc0 += __shfl_xor_sync(0xffffffffu, lacc0, m);
        lacc8 += __shfl_xor_sync(0xffffffffu, lacc8, m);
        zn0 += __shfl_xor_sync(0xffffffffu, zn0, m);
        zn8 += __shfl_xor_sync(0xffffffffu, zn8, m);
    }
    if (t4 == 0) {
        int row = qt0 + 16 * wid + g;
        g_zp[hh][b * TT + row] = zn0 / lacc0;
        g_zp[hh][b * TT + row + 8] = zn8 / lacc8;
    }
}

// ---------------------------------------------------------------------------
// bs[t] = sigmoid(sum_h zp[h][t] + b_eff)
__global__ __launch_bounds__(256) void zsig_kernel()
{
    int t = blockIdx.x * 256 + threadIdx.x;
    float z = g_zp[0][t] + g_zp[1][t] + g_zp[2][t] + g_zp[3][t] + g_weff[EE];
    g_bs[t] = 1.0f / (1.0f + expf(-z));
}

// ---------------------------------------------------------------------------
// Per batch: fp64 cumsum -> pid -> segment means (chunk sums + edges) -> proj
__global__ __launch_bounds__(256) void finalize_kernel(const float* __restrict__ w_pr,
                                                       const float* __restrict__ b_pr,
                                                       float* __restrict__ out)
{
    __shared__ float  sc[TT];
    __shared__ double sd[TT];
    __shared__ double part[256];
    __shared__ unsigned char pids[TT];
    __shared__ int starts[PP + 1];
    __shared__ float pe[PP][EE];

    const int b = blockIdx.x;
    const int tid = threadIdx.x;

    for (int t = tid; t < TT; t += 256) sc[t] = g_bs[b * TT + t];
    __syncthreads();

    {
        double s = 0.0;
#pragma unroll
        for (int i = 0; i < 8; i++) s += (double)sc[tid * 8 + i];
        part[tid] = s;
    }
    __syncthreads();
    if (tid == 0) {
        double run = 0.0;
        for (int i = 0; i < 256; i++) { double v = part[i]; part[i] = run; run += v; }
    }
    __syncthreads();
    {
        double c = part[tid];
#pragma unroll
        for (int i = 0; i < 8; i++) { c += (double)sc[tid * 8 + i]; sd[tid * 8 + i] = c; }
    }
    __syncthreads();

    double total = sd[TT - 1];
    double inv = 1.0 / fmax(total, 1e-6);
    for (int t = tid; t < TT; t += 256) {
        int p = (int)(sd[t] * inv * (double)PP);
        pids[t] = (unsigned char)(p > PP - 1 ? PP - 1 : p);
    }
    __syncthreads();

    if (tid == 0) {
        int cur = pids[0];
        for (int p = 0; p <= cur; p++) starts[p] = 0;
        for (int t = 1; t < TT; t++) {
            int p = pids[t];
            while (cur < p) starts[++cur] = t;
        }
        while (cur < PP) starts[++cur] = TT;
    }
    __syncthreads();

    // segment means via chunk sums + edge tokens; thread owns dim d = tid
    const float* hb = g_h + (size_t)b * TT * EE;
    for (int p = 0; p < PP; p++) {
        int s0 = starts[p], s1 = starts[p + 1];
        float sum = 0.f;
        int cs = (s0 + 63) >> 6, ce = s1 >> 6;
        if (cs <= ce) {
            for (int c = cs; c < ce; c++) sum += g_chs[b][c][tid];
            for (int t = s0; t < cs * 64; t++) sum += hb[(size_t)t * EE + tid];
            for (int t = ce * 64; t < s1; t++) sum += hb[(size_t)t * EE + tid];
        } else {
            for (int t = s0; t < s1; t++) sum += hb[(size_t)t * EE + tid];
        }
        float cnt = (float)(s1 - s0);
        pe[p][tid] = sum / fmaxf(cnt, 1.0f);
    }
    __syncthreads();

    // out[b][p][n] = pe[p].w_pr[n] + b_pr[n]; thread owns n = tid
    float bn = b_pr[tid];
    const float* wrow = w_pr + (size_t)tid * EE;
    for (int p = 0; p < PP; p++) {
        float a0 = 0.f, a1 = 0.f;
#pragma unroll 8
        for (int d = 0; d < EE; d += 2) {
            a0 += pe[p][d]     * wrow[d];
            a1 += pe[p][d + 1] * wrow[d + 1];
        }
        out[(size_t)(b * PP + p) * EE + tid] = bn + a0 + a1;
    }
}

// ---------------------------------------------------------------------------
extern "C" void kernel_launch(void* const* d_in, const int* in_sizes, int n_in,
                              void* d_out, int out_size)
{
    const float* x    = (const float*)d_in[0];
    const float* w_in = (const float*)d_in[1];
    const float* b_in = (const float*)d_in[2];
    const float* w_q  = (const float*)d_in[3];
    const float* b_q  = (const float*)d_in[4];
    const float* w_k  = (const float*)d_in[5];
    const float* b_k  = (const float*)d_in[6];
    const float* w_v  = (const float*)d_in[7];
    const float* b_v  = (const float*)d_in[8];
    const float* w_o  = (const float*)d_in[9];
    const float* b_o  = (const float*)d_in[10];
    const float* w_bd = (const float*)d_in[11];
    const float* b_bd = (const float*)d_in[12];
    const float* w_pr = (const float*)d_in[13];
    const float* b_pr = (const float*)d_in[14];
    float* out = (float*)d_out;

    float *ph;
    __half *pxh, *pxl, *phh, *phl, *pwh, *pwl;
    __half *pqh, *pql, *pkh, *pkl;
    cudaGetSymbolAddress((void**)&ph,  g_h);
    cudaGetSymbolAddress((void**)&pxh, g_xh);
    cudaGetSymbolAddress((void**)&pxl, g_xl);
    cudaGetSymbolAddress((void**)&phh, g_hh);
    cudaGetSymbolAddress((void**)&phl, g_hl);
    cudaGetSymbolAddress((void**)&pwh, g_wsh);
    cudaGetSymbolAddress((void**)&pwl, g_wsl);
    cudaGetSymbolAddress((void**)&pqh, g_qh);
    cudaGetSymbolAddress((void**)&pql, g_ql);
    cudaGetSymbolAddress((void**)&pkh, g_kh);
    cudaGetSymbolAddress((void**)&pkl, g_kl);

    weff_kernel<<<1, 256>>>(w_o, w_bd, b_o, b_bd);

    // splits
    split_kernel<<<BT*EE/4/256, 256>>>(x, pxh, pxl, BT*EE/4);
    split_kernel<<<EE*EE/4/256, 256>>>(w_in, pwh + 0*EE*EE, pwl + 0*EE*EE, EE*EE/4);
    split_kernel<<<EE*EE/4/256, 256>>>(w_q,  pwh + 1*EE*EE, pwl + 1*EE*EE, EE*EE/4);
    split_kernel<<<EE*EE/4/256, 256>>>(w_k,  pwh + 2*EE*EE, pwl + 2*EE*EE, EE*EE/4);
    split_kernel<<<EE*EE/4/256, 256>>>(w_v,  pwh + 3*EE*EE, pwl + 3*EE*EE, EE*EE/4);

    dim3 ggrid(BT / 64, EE / 64);
    // h = x @ w_in^T + b_in   (also emits hi/lo split of h)
    gemm_tc<<<ggrid, 128>>>(pxh, pxl, pwh + 0*EE*EE, pwl + 0*EE*EE, b_in, ph, phh, phl, 0);
    chs_kernel<<<dim3(BB, 32), 256>>>();
    // q, k
    gemm_tc<<<ggrid, 128>>>(phh, phl, pwh + 1*EE*EE, pwl + 1*EE*EE, b_q, nullptr, pqh, pql, 1);
    gemm_tc<<<ggrid, 128>>>(phh, phl, pwh + 2*EE*EE, pwl + 2*EE*EE, b_k, nullptr, pkh, pkl, 2);
    // v -> u = v . w_eff  (no v materialization)
    gemm_tc<<<ggrid, 128>>>(phh, phl, pwh + 3*EE*EE, pwl + 3*EE*EE, b_v, nullptr, nullptr, nullptr, 3);

    attn_mma<<<dim3(TT / 64, NBH), 128>>>();

    zsig_kernel<<<BT / 256, 256>>>();

    finalize_kernel<<<BB, 256>>>(w_pr, b_pr, out);
}